// round 1
// baseline (speedup 1.0000x reference)
#include <cuda_runtime.h>
#include <cuda_bf16.h>

// Shapes (fixed by the problem)
#define L_DIM 4
#define B_DIM 8
#define C_DIM 256
#define HW    4096           // 64*64
#define LBC   (L_DIM * B_DIM * C_DIM)   // 8192

// Scratch in device globals (no allocations allowed)
__device__ float g_gap[LBC];
__device__ float g_attn[LBC];

// ---------------------------------------------------------------------------
// Kernel 1: GAP over H,W. One block per (l,b,c) plane (4096 contiguous f32).
// 128 threads, each loads 8 float4 (32 floats), warp-shuffle reduce.
// ---------------------------------------------------------------------------
__global__ __launch_bounds__(128) void gap_kernel(const float* __restrict__ in) {
    const int bc = blockIdx.x;                     // 0..8191, linear (l,b,c)
    const float4* p = reinterpret_cast<const float4*>(in) + (size_t)bc * (HW / 4);
    const int t = threadIdx.x;

    float s = 0.0f;
#pragma unroll
    for (int k = 0; k < 8; ++k) {
        float4 v = p[t + k * 128];
        s += (v.x + v.y) + (v.z + v.w);
    }
#pragma unroll
    for (int o = 16; o > 0; o >>= 1)
        s += __shfl_xor_sync(0xffffffffu, s, o);

    __shared__ float sh[4];
    if ((t & 31) == 0) sh[t >> 5] = s;
    __syncthreads();
    if (t == 0)
        g_gap[bc] = (sh[0] + sh[1] + sh[2] + sh[3]) * (1.0f / (float)HW);
}

// ---------------------------------------------------------------------------
// Kernel 2: scores = gap @ W^T, softmax over L per (b, d). 8 blocks (one per b),
// 256 threads (one per output channel d).
// ---------------------------------------------------------------------------
__global__ __launch_bounds__(C_DIM) void attn_kernel(const float* __restrict__ Wlin) {
    const int b = blockIdx.x;
    const int d = threadIdx.x;

    __shared__ float gs[L_DIM][C_DIM];
    for (int i = threadIdx.x; i < L_DIM * C_DIM; i += blockDim.x) {
        int l = i >> 8;
        int c = i & 255;
        gs[l][c] = g_gap[(l * B_DIM + b) * C_DIM + c];
    }
    __syncthreads();

    float acc[L_DIM] = {0.f, 0.f, 0.f, 0.f};
    const float* wr = Wlin + (size_t)d * C_DIM;
#pragma unroll 4
    for (int c = 0; c < C_DIM; ++c) {
        float w = wr[c];
#pragma unroll
        for (int l = 0; l < L_DIM; ++l)
            acc[l] = fmaf(w, gs[l][c], acc[l]);
    }

    float m = fmaxf(fmaxf(acc[0], acc[1]), fmaxf(acc[2], acc[3]));
    float e[L_DIM];
    float sum = 0.0f;
#pragma unroll
    for (int l = 0; l < L_DIM; ++l) {
        e[l] = __expf(acc[l] - m);
        sum += e[l];
    }
    float inv = 1.0f / sum;
#pragma unroll
    for (int l = 0; l < L_DIM; ++l)
        g_attn[(l * B_DIM + b) * C_DIM + d] = e[l] * inv;
}

// ---------------------------------------------------------------------------
// Kernel 3: out = in * attn (broadcast per (l,b,c) plane).
// One block per plane; 256 threads x 4 float4 each = 4096 floats.
// ---------------------------------------------------------------------------
__global__ __launch_bounds__(256) void scale_kernel(const float* __restrict__ in,
                                                    float* __restrict__ out) {
    const int bc = blockIdx.x;
    const float a = g_attn[bc];
    const float4* p = reinterpret_cast<const float4*>(in) + (size_t)bc * (HW / 4);
    float4* o = reinterpret_cast<float4*>(out) + (size_t)bc * (HW / 4);
    const int t = threadIdx.x;
#pragma unroll
    for (int k = 0; k < 4; ++k) {
        float4 v = p[t + k * 256];
        v.x *= a; v.y *= a; v.z *= a; v.w *= a;
        o[t + k * 256] = v;
    }
}

extern "C" void kernel_launch(void* const* d_in, const int* in_sizes, int n_in,
                              void* d_out, int out_size) {
    const float* inputs = (const float*)d_in[0];   // [L,B,C,H,W] f32
    const float* Wlin   = (const float*)d_in[1];   // [C,C] f32
    float* out = (float*)d_out;

    gap_kernel<<<LBC, 128>>>(inputs);
    attn_kernel<<<B_DIM, C_DIM>>>(Wlin);
    scale_kernel<<<LBC, 256>>>(inputs, out);
}